// round 13
// baseline (speedup 1.0000x reference)
#include <cuda_runtime.h>

#define BB 10
#define CC 3
#define HH 50
#define WW 101
#define KK 4096
#define KSPLIT 5
#define KCH 820

#define HP 56
#define WP 110
#define SLICE (HP*WP)                 // 6160
#define GRIDP_N (BB*CC*SLICE)

#define P1_PAD_N (BB*32*16*30)
#define P2_PAD_N (BB*64*8*14)

__device__ int   g_ord[KSPLIT*BB*CC*5056];
__device__ float g_gridp[GRIDP_N];
__device__ float g_p1[P1_PAD_N];   // zero-initialized; borders never written
__device__ float g_p2[P2_PAD_N];   // zero-initialized; borders never written
__device__ float g_gap[BB*128];

// packed fp32x2 FMA (sm_100a): acc += a * b elementwise, exact fp32
__device__ __forceinline__ void ffma2(float2& acc, float2 a, float2 b) {
    union { float2 f; unsigned long long u; } ua, ub, uc;
    ua.f = a; ub.f = b; uc.f = acc;
    asm("fma.rn.f32x2 %0, %1, %2, %0;" : "+l"(uc.u) : "l"(ua.u), "l"(ub.u));
    acc = uc.f;
}
__device__ __forceinline__ float2 bcast2(float v) { return make_float2(v, v); }

// ---------------------------------------------------------------------------
// 1a. Scatter: 150 blocks = (bc, ksplit). smem atomicMax over this split's points.
__global__ void scatter_split(const int* __restrict__ x) {
    __shared__ int s_ord[HH*WW];
    int bc = blockIdx.x / KSPLIT, ks = blockIdx.x % KSPLIT;
    for (int i = threadIdx.x; i < HH*WW; i += 1024) s_ord[i] = -1;
    __syncthreads();
    const int2* xp = (const int2*)x;
    int k0 = ks * KCH;
    int k1 = k0 + KCH; if (k1 > KK + 1) k1 = KK + 1;
    for (int k = k0 + threadIdx.x; k < k1; k += 1024) {
        int col, row;
        if (k == 0) { col = 50; row = 48; }
        else { int2 p = xp[bc*KK + k - 1]; col = p.x; row = p.y; }
        int base = row * WW + col;
        int o = k * 10;
        atomicMax(&s_ord[base-WW-1], o+0);
        atomicMax(&s_ord[base-WW  ], o+1);
        atomicMax(&s_ord[base-WW+1], o+2);
        atomicMax(&s_ord[base-1   ], o+3);
        atomicMax(&s_ord[base+1   ], o+5);
        atomicMax(&s_ord[base+WW-1], o+6);
        atomicMax(&s_ord[base+WW  ], o+7);
        atomicMax(&s_ord[base+WW+1], o+8);
        atomicMax(&s_ord[base     ], o+9);
    }
    __syncthreads();
    int* dst = g_ord + (ks*BB*CC + bc) * 5056;
    for (int i = threadIdx.x; i < HH*WW; i += 1024) dst[i] = s_ord[i];
}

// 1b. Convert: max over splits -> padded float grid [56][110].
__global__ void convert_grid() {
    int t = blockIdx.x * 256 + threadIdx.x;
    if (t >= GRIDP_N) return;
    int bc = t / SLICE, q = t % SLICE;
    int r = q / WP, cl = q % WP;
    float v = 0.f;
    if (r >= 3 && r < 3+HH && cl >= 3 && cl < 3+WW) {
        int cell = (r-3)*WW + (cl-3);
        int o = -1;
#pragma unroll
        for (int ks = 0; ks < KSPLIT; ks++)
            o = max(o, g_ord[(ks*BB*CC + bc)*5056 + cell]);
        if (o >= 0) v = ((o % 10) == 9) ? 1.0f : 0.5f;
    }
    g_gridp[bc*SLICE + q] = v;
}

// ---------------------------------------------------------------------------
// 2. conv1 7x7 s2 (3->32) + relu + pool 3x3 s2. 320 blocks x 128 thr (R6-proven).
__global__ void __launch_bounds__(128) conv1_pool1(const float* __restrict__ w1,
                                                   const float* __restrict__ b1) {
    extern __shared__ float sm[];
    float* s_in = sm;              // 6270
    float* s_w  = sm + 6270;       // 588
    float* s_c  = sm + 6860;       // 1428
    int bx = blockIdx.x;
    int b = bx >> 5, r = bx & 31;
    int cq = r >> 2, g = r & 3;
    int co0 = cq * 4;
    int row0 = 12 * g;
    {
        const float2* src = (const float2*)(g_gridp + b * 3 * SLICE);
        float2* dst = (float2*)s_in;
        for (int i = threadIdx.x; i < 3*19*55; i += 128) {
            int ci = i / (19*55), rr = (i % (19*55)) / 55, cc = i % 55;
            dst[i] = src[ci*(SLICE/2) + (row0+rr)*55 + cc];
        }
        for (int i = threadIdx.x; i < 588; i += 128) {
            int coin = i & 1, pr = (i >> 1) & 1, j = i >> 2;
            s_w[i] = w1[(co0 + pr*2 + coin) * 147 + j];
        }
    }
    __syncthreads();
    if (threadIdx.x < 119) {
        int oh = threadIdx.x / 17, owt = threadIdx.x % 17;
        int ow0 = owt * 3;
        float2 bias0 = make_float2(b1[co0],   b1[co0+1]);
        float2 bias1 = make_float2(b1[co0+2], b1[co0+3]);
        float2 acc[3][2];
#pragma unroll
        for (int t = 0; t < 3; t++) { acc[t][0] = bias0; acc[t][1] = bias1; }
        const float2* wv = (const float2*)s_w;
#pragma unroll
        for (int ci = 0; ci < 3; ci++) {
#pragma unroll
            for (int kh = 0; kh < 7; kh++) {
                const float2* rp = (const float2*)(s_in + ci*2090 + (oh*2 + kh)*110 + ow0*2);
                float2 q0 = rp[0], q1 = rp[1], q2 = rp[2], q3 = rp[3], q4 = rp[4], q5 = rp[5];
                float v[11] = {q0.x,q0.y,q1.x,q1.y,q2.x,q2.y,q3.x,q3.y,q4.x,q4.y,q5.x};
#pragma unroll
                for (int kw = 0; kw < 7; kw++) {
                    float2 wa = wv[(ci*49 + kh*7 + kw)*2 + 0];
                    float2 wb = wv[(ci*49 + kh*7 + kw)*2 + 1];
#pragma unroll
                    for (int t = 0; t < 3; t++) {
                        float2 iv = bcast2(v[kw + 2*t]);
                        ffma2(acc[t][0], iv, wa);
                        ffma2(acc[t][1], iv, wb);
                    }
                }
            }
        }
#pragma unroll
        for (int t = 0; t < 3; t++) {
            s_c[0*357 + oh*51 + ow0 + t] = fmaxf(acc[t][0].x, 0.f);
            s_c[1*357 + oh*51 + ow0 + t] = fmaxf(acc[t][0].y, 0.f);
            s_c[2*357 + oh*51 + ow0 + t] = fmaxf(acc[t][1].x, 0.f);
            s_c[3*357 + oh*51 + ow0 + t] = fmaxf(acc[t][1].y, 0.f);
        }
    }
    __syncthreads();
    for (int q = threadIdx.x; q < 300; q += 128) {
        int u = q / 75, qq = q % 75, pr2 = qq / 25, pc = qq % 25;
        const float* c = s_c + u*357 + (pr2*2)*51 + pc*2;
        float m = fmaxf(fmaxf(c[0], c[1]), c[2]);
        m = fmaxf(m, fmaxf(fmaxf(c[51], c[52]), c[53]));
        m = fmaxf(m, fmaxf(fmaxf(c[102], c[103]), c[104]));
        g_p1[((b*32 + co0 + u) * 16 + (2 + 3*g + pr2)) * 30 + (2 + pc)] = m;
    }
}

// ---------------------------------------------------------------------------
// 3. conv2 5x5 (32->64) + relu + pool 2x2.
//    Grid = (b10 x cog16 of 4co x ohh2) = 320 blocks x 240 thr.
//    Thread: ciq8(4ci) x oh6 x owt5; acc[5][2] f2 = 4co x 5ow.
//    Partial-sum scratch ALIASED over dead s_in region.
__global__ void __launch_bounds__(240, 2) conv2_pool2(const float* __restrict__ w2,
                                                      const float* __restrict__ b2) {
    extern __shared__ float sm[];
    float*  s_part = sm;                  // 240*20 = 4800 (aliases s_in)
    float*  s_c    = sm + 4800;           // 600 (aliases s_in)
    float*  s_in   = sm;                  // 32*300 = 9600 (dead after main loop)
    float*  s_w    = sm + 9600;           // 3200: [j][cp][coin]
    int bx = blockIdx.x;
    int b = bx >> 5, r = bx & 31;
    int cog = r >> 1, ohh = r & 1;
    int co0 = cog * 4;
    int oh_base = ohh * 6;
    {
        const float2* src = (const float2*)g_p1;
        float2* dst = (float2*)s_in;
        for (int i = threadIdx.x; i < 4800; i += 240) {
            int ci = i / 150, rem = i % 150;
            int rr = rem / 15, c = rem % 15;
            dst[ci*150 + rr*15 + c] =
                src[(b*15360 + ci*480 + (oh_base + rr)*30) / 2 + c];
        }
        for (int i = threadIdx.x; i < 3200; i += 240) {
            int coin = i & 1, cp = (i >> 1) & 1, j = i >> 2;
            s_w[i] = w2[(co0 + cp*2 + coin) * 800 + j];
        }
    }
    __syncthreads();
    float2 acc[5][2];
    {
        int ciq = threadIdx.x / 30, rem = threadIdx.x % 30;
        int oh_l = rem / 5, ow0 = (rem % 5) * 5;
#pragma unroll
        for (int t = 0; t < 5; t++) { acc[t][0] = make_float2(0.f,0.f); acc[t][1] = make_float2(0.f,0.f); }
        const float2* wv = (const float2*)s_w;
        int ci0 = ciq * 4;
#pragma unroll
        for (int cii = 0; cii < 4; cii++) {
            int ci = ci0 + cii;
#pragma unroll
            for (int kh = 0; kh < 5; kh++) {
                const float* rp = s_in + ci*300 + (oh_l + kh)*30 + ow0;
                float v[9];
#pragma unroll
                for (int m = 0; m < 9; m++) v[m] = rp[m];
                float2 wA[5], wB[5];
#pragma unroll
                for (int kw = 0; kw < 5; kw++) {
                    wA[kw] = wv[(ci*25 + kh*5 + kw)*2 + 0];
                    wB[kw] = wv[(ci*25 + kh*5 + kw)*2 + 1];
                }
#pragma unroll
                for (int kw = 0; kw < 5; kw++)
#pragma unroll
                    for (int t = 0; t < 5; t++) {
                        float2 iv = bcast2(v[kw+t]);
                        ffma2(acc[t][0], iv, wA[kw]);
                        ffma2(acc[t][1], iv, wB[kw]);
                    }
            }
        }
    }
    __syncthreads();   // all s_in reads done before aliased writes
    {
        float* pp = s_part + threadIdx.x * 20;
#pragma unroll
        for (int t = 0; t < 5; t++) {
            pp[t*4 + 0] = acc[t][0].x; pp[t*4 + 1] = acc[t][0].y;
            pp[t*4 + 2] = acc[t][1].x; pp[t*4 + 3] = acc[t][1].y;
        }
    }
    __syncthreads();
    for (int o = threadIdx.x; o < 600; o += 240) {
        int co_l = o / 150, pos = o % 150;
        int oh_l = pos / 25, ow = pos % 25;
        int owt = ow / 5, t = ow % 5;
        int cp = co_l >> 1, coin = co_l & 1;
        float v = b2[co0 + co_l];
        int off = (oh_l*5 + owt)*20 + t*4 + cp*2 + coin;
#pragma unroll
        for (int q = 0; q < 8; q++) v += s_part[q*600 + off];
        s_c[co_l*150 + pos] = fmaxf(v, 0.f);
    }
    __syncthreads();
    if (threadIdx.x < 144) {
        int u = threadIdx.x / 36, rc = threadIdx.x % 36;
        int rl = rc / 12, cl = rc % 12;
        const float* c = s_c + u*150 + (rl*2)*25 + cl*2;
        float v = fmaxf(fmaxf(c[0], c[1]), fmaxf(c[25], c[26]));
        g_p2[((b*64 + co0 + u) * 8 + (ohh*3 + rl + 1)) * 14 + (cl + 1)] = v;
    }
}

// ---------------------------------------------------------------------------
// 4. conv3 3x3 (64->128) + relu + pool 2x2 + global-avg.
//    Grid = (b10 x cog32 of 4co) = 320 blocks x 192 thr.
//    Thread: ciq16(4ci) x oh6 x owh2; acc[6][2] f2 = 4co x 6ow.
//    Partial scratch + s_c + s_p ALIASED over dead s_in region.
__global__ void __launch_bounds__(192, 4) conv3_gap(const float* __restrict__ w3,
                                                    const float* __restrict__ b3) {
    extern __shared__ float sm[];
    float*  s_part = sm;                  // 192*24 = 4608 (aliases s_in)
    float*  s_c    = sm + 4608;           // 288 (aliases s_in)
    float*  s_p    = sm + 4896;           // 72 (aliases s_in)
    float*  s_in   = sm;                  // 64*114 = 7296 (dead after main loop)
    float*  s_w    = sm + 7296;           // 2304: [j][cp][coin]
    int b = blockIdx.x >> 5, cog = blockIdx.x & 31;
    int cb = cog * 4;
    {
        const float2* src = (const float2*)(g_p2 + b * 7168);
        for (int i = threadIdx.x; i < 3584; i += 192) {
            int ci = i / 56, rem = i % 56;
            *(float2*)(s_in + ci*114 + rem*2) = src[i];
        }
        for (int i = threadIdx.x; i < 2304; i += 192) {
            int coin = i & 1, cp = (i >> 1) & 1, j = i >> 2;
            s_w[i] = w3[(cb + cp*2 + coin) * 576 + j];
        }
    }
    __syncthreads();
    float2 acc[6][2];
    {
        int ciq = threadIdx.x / 12, rem = threadIdx.x % 12;
        int oh = rem >> 1, owh = rem & 1;
        int ow0 = owh * 6;
#pragma unroll
        for (int t = 0; t < 6; t++) { acc[t][0] = make_float2(0.f,0.f); acc[t][1] = make_float2(0.f,0.f); }
        const float2* wv = (const float2*)s_w;
        int ci0 = ciq * 4;
#pragma unroll
        for (int cii = 0; cii < 4; cii++) {
            int ci = ci0 + cii;
#pragma unroll
            for (int kh = 0; kh < 3; kh++) {
                const float2* rp = (const float2*)(s_in + ci*114 + (oh + kh)*14 + ow0);
                float v[8];
#pragma unroll
                for (int m = 0; m < 4; m++) { float2 p = rp[m]; v[2*m] = p.x; v[2*m+1] = p.y; }
                float2 wA[3], wB[3];
#pragma unroll
                for (int kw = 0; kw < 3; kw++) {
                    wA[kw] = wv[(ci*9 + kh*3 + kw)*2 + 0];
                    wB[kw] = wv[(ci*9 + kh*3 + kw)*2 + 1];
                }
#pragma unroll
                for (int kw = 0; kw < 3; kw++)
#pragma unroll
                    for (int t = 0; t < 6; t++) {
                        float2 iv = bcast2(v[kw+t]);
                        ffma2(acc[t][0], iv, wA[kw]);
                        ffma2(acc[t][1], iv, wB[kw]);
                    }
            }
        }
    }
    __syncthreads();   // all s_in reads done before aliased writes
    {
        float* pp = s_part + threadIdx.x * 24;
#pragma unroll
        for (int t = 0; t < 6; t++) {
            pp[t*4 + 0] = acc[t][0].x; pp[t*4 + 1] = acc[t][0].y;
            pp[t*4 + 2] = acc[t][1].x; pp[t*4 + 3] = acc[t][1].y;
        }
    }
    __syncthreads();
    for (int o = threadIdx.x; o < 288; o += 192) {
        int co_l = o / 72, pos = o % 72;
        int oh2 = pos / 12, ow = pos % 12;
        int owh = ow / 6, t = ow % 6;
        int cp = co_l >> 1, coin = co_l & 1;
        float v = b3[cb + co_l];
        int off = (oh2*2 + owh)*24 + t*4 + cp*2 + coin;
#pragma unroll
        for (int q = 0; q < 16; q++) v += s_part[q*288 + off];
        s_c[co_l*72 + pos] = fmaxf(v, 0.f);
    }
    __syncthreads();
    if (threadIdx.x < 72) {
        int co_l = threadIdx.x / 18, cell = threadIdx.x % 18;
        int ph = cell / 6, pw = cell % 6;
        const float* c = s_c + co_l*72 + (ph*2)*12 + pw*2;
        s_p[threadIdx.x] = fmaxf(fmaxf(c[0], c[1]), fmaxf(c[12], c[13]));
    }
    __syncthreads();
    if (threadIdx.x < 4) {
        float s = 0.f;
#pragma unroll
        for (int i = 0; i < 18; i++) s += s_p[threadIdx.x*18 + i];
        g_gap[b*128 + cb + threadIdx.x] = s * (1.0f/18.0f);
    }
}

// ---------------------------------------------------------------------------
// 5. fc: coalesced. 8 lanes per output row; LDG.128; shfl-tree reduce.
__global__ void __launch_bounds__(128) fc_fused(const float* __restrict__ wl1,
                                                const float* __restrict__ bl1,
                                                const float* __restrict__ wl2,
                                                const float* __restrict__ bl2,
                                                float* __restrict__ out) {
    __shared__ float s_g[128];
    __shared__ float s_h[128];
    int b = blockIdx.x, tid = threadIdx.x;
    s_g[tid] = g_gap[b*128 + tid];
    __syncthreads();
    const float4* g4 = (const float4*)s_g;
#pragma unroll
    for (int pass = 0; pass < 8; pass++) {
        int t = pass*16 + (tid >> 3);
        int j = tid & 7;
        const float4* wr = (const float4*)(wl1 + t*128);
        float s = 0.f;
#pragma unroll
        for (int k = 0; k < 4; k++) {
            float4 w4 = wr[j + k*8];
            float4 gv = g4[j + k*8];
            s += w4.x*gv.x + w4.y*gv.y + w4.z*gv.z + w4.w*gv.w;
        }
        s += __shfl_down_sync(0xffffffffu, s, 4);
        s += __shfl_down_sync(0xffffffffu, s, 2);
        s += __shfl_down_sync(0xffffffffu, s, 1);
        if (j == 0) s_h[t] = fmaxf(s + bl1[t], 0.f);
    }
    __syncthreads();
    const float4* h4 = (const float4*)s_h;
    if (tid < 40) {
        int t = tid >> 3, j = tid & 7;
        const float4* wr = (const float4*)(wl2 + t*128);
        float s = 0.f;
#pragma unroll
        for (int k = 0; k < 4; k++) {
            float4 w4 = wr[j + k*8];
            float4 hv = h4[j + k*8];
            s += w4.x*hv.x + w4.y*hv.y + w4.z*hv.z + w4.w*hv.w;
        }
        s += __shfl_down_sync(0xffffffffu, s, 4);
        s += __shfl_down_sync(0xffffffffu, s, 2);
        s += __shfl_down_sync(0xffffffffu, s, 1);
        if (j == 0) out[b*5 + t] = s + bl2[t];
    }
}

extern "C" void kernel_launch(void* const* d_in, const int* in_sizes, int n_in,
                              void* d_out, int out_size) {
    const int*   x   = (const int*)  d_in[0];
    const float* w1  = (const float*)d_in[1];
    const float* b1  = (const float*)d_in[2];
    const float* w2  = (const float*)d_in[3];
    const float* b2  = (const float*)d_in[4];
    const float* w3  = (const float*)d_in[5];
    const float* b3  = (const float*)d_in[6];
    const float* wl1 = (const float*)d_in[7];
    const float* bl1 = (const float*)d_in[8];
    const float* wl2 = (const float*)d_in[9];
    const float* bl2 = (const float*)d_in[10];
    float* out = (float*)d_out;

    const int smem1 = (6270 + 588 + 1428) * 4;      // 33144 B
    const int smem2 = (9600 + 3200) * 4;            // 51200 B
    const int smem3 = (7296 + 2304) * 4;            // 38400 B
    cudaFuncSetAttribute(conv1_pool1, cudaFuncAttributeMaxDynamicSharedMemorySize, smem1);
    cudaFuncSetAttribute(conv2_pool2, cudaFuncAttributeMaxDynamicSharedMemorySize, smem2);
    cudaFuncSetAttribute(conv3_gap,   cudaFuncAttributeMaxDynamicSharedMemorySize, smem3);

    scatter_split<<<BB*CC*KSPLIT, 1024>>>(x);
    convert_grid <<<(GRIDP_N + 255) / 256, 256>>>();
    conv1_pool1  <<<BB*32, 128, smem1>>>(w1, b1);
    conv2_pool2  <<<BB*32, 240, smem2>>>(w2, b2);
    conv3_gap    <<<BB*32, 192, smem3>>>(w3, b3);
    fc_fused     <<<BB, 128>>>(wl1, bl1, wl2, bl2, out);
}

// round 14
// speedup vs baseline: 1.1243x; 1.1243x over previous
#include <cuda_runtime.h>

#define BB 10
#define CC 3
#define HH 50
#define WW 101
#define KK 4096
#define KSPLIT 5
#define KCH 820

#define HP 56
#define WP 110
#define SLICE (HP*WP)                 // 6160
#define GRIDP_N (BB*CC*SLICE)

#define P1_PAD_N (BB*32*16*30)
#define P2_PAD_N (BB*64*8*14)

__device__ int   g_ord[KSPLIT*BB*CC*5056];
__device__ float g_gridp[GRIDP_N];
__device__ float g_p1[P1_PAD_N];   // zero-initialized; borders never written
__device__ float g_p2[P2_PAD_N];   // zero-initialized; borders never written
__device__ float g_gap[BB*128];

// packed fp32x2 FMA (sm_100a): acc += a * b elementwise, exact fp32
__device__ __forceinline__ void ffma2(float2& acc, float2 a, float2 b) {
    union { float2 f; unsigned long long u; } ua, ub, uc;
    ua.f = a; ub.f = b; uc.f = acc;
    asm("fma.rn.f32x2 %0, %1, %2, %0;" : "+l"(uc.u) : "l"(ua.u), "l"(ub.u));
    acc = uc.f;
}
__device__ __forceinline__ float2 bcast2(float v) { return make_float2(v, v); }

// ---------------------------------------------------------------------------
// 1a. Scatter: 150 blocks = (bc, ksplit). smem atomicMax over this split's points.
__global__ void scatter_split(const int* __restrict__ x) {
    __shared__ int s_ord[HH*WW];
    int bc = blockIdx.x / KSPLIT, ks = blockIdx.x % KSPLIT;
    for (int i = threadIdx.x; i < HH*WW; i += 1024) s_ord[i] = -1;
    __syncthreads();
    const int2* xp = (const int2*)x;
    int k0 = ks * KCH;
    int k1 = k0 + KCH; if (k1 > KK + 1) k1 = KK + 1;
    for (int k = k0 + threadIdx.x; k < k1; k += 1024) {
        int col, row;
        if (k == 0) { col = 50; row = 48; }
        else { int2 p = xp[bc*KK + k - 1]; col = p.x; row = p.y; }
        int base = row * WW + col;
        int o = k * 10;
        atomicMax(&s_ord[base-WW-1], o+0);
        atomicMax(&s_ord[base-WW  ], o+1);
        atomicMax(&s_ord[base-WW+1], o+2);
        atomicMax(&s_ord[base-1   ], o+3);
        atomicMax(&s_ord[base+1   ], o+5);
        atomicMax(&s_ord[base+WW-1], o+6);
        atomicMax(&s_ord[base+WW  ], o+7);
        atomicMax(&s_ord[base+WW+1], o+8);
        atomicMax(&s_ord[base     ], o+9);
    }
    __syncthreads();
    int* dst = g_ord + (ks*BB*CC + bc) * 5056;
    for (int i = threadIdx.x; i < HH*WW; i += 1024) dst[i] = s_ord[i];
}

// 1b. Convert: max over splits -> padded float grid [56][110].
__global__ void convert_grid() {
    int t = blockIdx.x * 256 + threadIdx.x;
    if (t >= GRIDP_N) return;
    int bc = t / SLICE, q = t % SLICE;
    int r = q / WP, cl = q % WP;
    float v = 0.f;
    if (r >= 3 && r < 3+HH && cl >= 3 && cl < 3+WW) {
        int cell = (r-3)*WW + (cl-3);
        int o = -1;
#pragma unroll
        for (int ks = 0; ks < KSPLIT; ks++)
            o = max(o, g_ord[(ks*BB*CC + bc)*5056 + cell]);
        if (o >= 0) v = ((o % 10) == 9) ? 1.0f : 0.5f;
    }
    g_gridp[bc*SLICE + q] = v;
}

// ---------------------------------------------------------------------------
// 2. conv1 7x7 s2 (3->32) + relu + pool 3x3 s2. 320 blocks x 128 thr (R6-proven).
__global__ void __launch_bounds__(128) conv1_pool1(const float* __restrict__ w1,
                                                   const float* __restrict__ b1) {
    extern __shared__ float sm[];
    float* s_in = sm;              // 6270
    float* s_w  = sm + 6270;       // 588
    float* s_c  = sm + 6860;       // 1428
    int bx = blockIdx.x;
    int b = bx >> 5, r = bx & 31;
    int cq = r >> 2, g = r & 3;
    int co0 = cq * 4;
    int row0 = 12 * g;
    {
        const float2* src = (const float2*)(g_gridp + b * 3 * SLICE);
        float2* dst = (float2*)s_in;
        for (int i = threadIdx.x; i < 3*19*55; i += 128) {
            int ci = i / (19*55), rr = (i % (19*55)) / 55, cc = i % 55;
            dst[i] = src[ci*(SLICE/2) + (row0+rr)*55 + cc];
        }
        for (int i = threadIdx.x; i < 588; i += 128) {
            int coin = i & 1, pr = (i >> 1) & 1, j = i >> 2;
            s_w[i] = w1[(co0 + pr*2 + coin) * 147 + j];
        }
    }
    __syncthreads();
    if (threadIdx.x < 119) {
        int oh = threadIdx.x / 17, owt = threadIdx.x % 17;
        int ow0 = owt * 3;
        float2 bias0 = make_float2(b1[co0],   b1[co0+1]);
        float2 bias1 = make_float2(b1[co0+2], b1[co0+3]);
        float2 acc[3][2];
#pragma unroll
        for (int t = 0; t < 3; t++) { acc[t][0] = bias0; acc[t][1] = bias1; }
        const float2* wv = (const float2*)s_w;
#pragma unroll
        for (int ci = 0; ci < 3; ci++) {
#pragma unroll
            for (int kh = 0; kh < 7; kh++) {
                const float2* rp = (const float2*)(s_in + ci*2090 + (oh*2 + kh)*110 + ow0*2);
                float2 q0 = rp[0], q1 = rp[1], q2 = rp[2], q3 = rp[3], q4 = rp[4], q5 = rp[5];
                float v[11] = {q0.x,q0.y,q1.x,q1.y,q2.x,q2.y,q3.x,q3.y,q4.x,q4.y,q5.x};
#pragma unroll
                for (int kw = 0; kw < 7; kw++) {
                    float2 wa = wv[(ci*49 + kh*7 + kw)*2 + 0];
                    float2 wb = wv[(ci*49 + kh*7 + kw)*2 + 1];
#pragma unroll
                    for (int t = 0; t < 3; t++) {
                        float2 iv = bcast2(v[kw + 2*t]);
                        ffma2(acc[t][0], iv, wa);
                        ffma2(acc[t][1], iv, wb);
                    }
                }
            }
        }
#pragma unroll
        for (int t = 0; t < 3; t++) {
            s_c[0*357 + oh*51 + ow0 + t] = fmaxf(acc[t][0].x, 0.f);
            s_c[1*357 + oh*51 + ow0 + t] = fmaxf(acc[t][0].y, 0.f);
            s_c[2*357 + oh*51 + ow0 + t] = fmaxf(acc[t][1].x, 0.f);
            s_c[3*357 + oh*51 + ow0 + t] = fmaxf(acc[t][1].y, 0.f);
        }
    }
    __syncthreads();
    for (int q = threadIdx.x; q < 300; q += 128) {
        int u = q / 75, qq = q % 75, pr2 = qq / 25, pc = qq % 25;
        const float* c = s_c + u*357 + (pr2*2)*51 + pc*2;
        float m = fmaxf(fmaxf(c[0], c[1]), c[2]);
        m = fmaxf(m, fmaxf(fmaxf(c[51], c[52]), c[53]));
        m = fmaxf(m, fmaxf(fmaxf(c[102], c[103]), c[104]));
        g_p1[((b*32 + co0 + u) * 16 + (2 + 3*g + pr2)) * 30 + (2 + pc)] = m;
    }
}

// ---------------------------------------------------------------------------
// 3. conv2 5x5 (32->64) + relu + pool 2x2. R12-proven shape (320 x 480),
//    with s_part/s_c ALIASED over dead s_in -> smem 67.8KB, 3 blocks/SM.
__global__ void __launch_bounds__(480, 3) conv2_pool2(const float* __restrict__ w2,
                                                      const float* __restrict__ b2) {
    extern __shared__ float sm[];
    float* s_part = sm;            // 4800 (aliases s_in, dead after main loop)
    float* s_c    = sm + 4800;     // 600 (aliases s_in)
    float* s_in   = sm;            // 15360
    float* s_w    = sm + 15360;    // 1600
    int b = blockIdx.x >> 5, cog = blockIdx.x & 31;
    int co0 = cog * 2;
    {
        const float4* src = (const float4*)(g_p1 + b * 15360);
        float4* dst = (float4*)s_in;
        for (int i = threadIdx.x; i < 3840; i += 480) dst[i] = src[i];
        for (int i = threadIdx.x; i < 1600; i += 480)
            s_w[i] = w2[(co0 + (i & 1)) * 800 + (i >> 1)];
    }
    __syncthreads();
    float2 acc[5] = {};
    int ciq = threadIdx.x / 60, rem = threadIdx.x % 60;
    int oh = rem / 5, ow0 = (rem % 5) * 5;
    {
        const float2* wv = (const float2*)s_w;
        int ci0 = ciq * 4;
#pragma unroll
        for (int cii = 0; cii < 4; cii++) {
            int ci = ci0 + cii;
#pragma unroll
            for (int kh = 0; kh < 5; kh++) {
                const float* rp = s_in + ci*480 + (oh + kh)*30 + ow0;
                float v[9];
#pragma unroll
                for (int m = 0; m < 9; m++) v[m] = rp[m];
                float2 w[5];
#pragma unroll
                for (int kw = 0; kw < 5; kw++) w[kw] = wv[ci*25 + kh*5 + kw];
#pragma unroll
                for (int kw = 0; kw < 5; kw++)
#pragma unroll
                    for (int t = 0; t < 5; t++)
                        ffma2(acc[t], bcast2(v[kw+t]), w[kw]);
            }
        }
    }
    __syncthreads();   // all s_in reads complete before aliased writes
    {
        float* pp = s_part + ciq*600 + oh*50 + ow0*2;
#pragma unroll
        for (int t = 0; t < 5; t++) { pp[t*2] = acc[t].x; pp[t*2+1] = acc[t].y; }
    }
    __syncthreads();
    for (int o = threadIdx.x; o < 600; o += 480) {
        int coin = o & 1, pos = o >> 1;
        float v = b2[co0 + coin];
#pragma unroll
        for (int q = 0; q < 8; q++) v += s_part[q*600 + o];
        s_c[coin*300 + pos] = fmaxf(v, 0.f);
    }
    __syncthreads();
    if (threadIdx.x < 144) {
        int u = threadIdx.x / 72, rc = threadIdx.x % 72;
        int rr = rc / 12, cl = rc % 12;
        const float* c = s_c + u*300 + (rr*2)*25 + cl*2;
        float v = fmaxf(fmaxf(c[0], c[1]), fmaxf(c[25], c[26]));
        g_p2[((b*64 + co0 + u) * 8 + (rr + 1)) * 14 + (cl + 1)] = v;
    }
}

// ---------------------------------------------------------------------------
// 4. conv3 3x3 (64->128) + relu + pool 2x2 + global-avg. R7/R12-proven shape
//    (320 x 384), with s_part/s_c/s_p ALIASED over dead s_in -> 38.4KB smem.
__global__ void __launch_bounds__(384, 3) conv3_gap(const float* __restrict__ w3,
                                                    const float* __restrict__ b3) {
    extern __shared__ float sm[];
    float* s_part = sm;            // 4608 (aliases s_in, dead after main loop)
    float* s_c    = sm + 4608;     // 288 (aliases s_in)
    float* s_p    = sm + 4896;     // 72 (aliases s_in)
    float* s_in   = sm;            // 7296
    float* s_w    = sm + 7296;     // 2304
    int b = blockIdx.x >> 5, cog = blockIdx.x & 31;
    int cb = cog * 4;
    {
        const float2* src = (const float2*)(g_p2 + b * 7168);
        for (int i = threadIdx.x; i < 3584; i += 384) {
            int ci = i / 56, rem = i % 56;
            *(float2*)(s_in + ci*114 + rem*2) = src[i];
        }
        for (int i = threadIdx.x; i < 2304; i += 384) {
            int coin = i & 1, pr = (i >> 1) & 1, j = i >> 2;
            s_w[i] = w3[(cb + pr*2 + coin) * 576 + j];
        }
    }
    __syncthreads();
    float2 acc[6] = {};
    int ciq = threadIdx.x / 24, rem = threadIdx.x % 24;
    int pair = rem / 12, oh = (rem % 12) >> 1, owh = rem & 1;
    {
        int ow0 = owh * 6;
        int ci0 = ciq * 4;
        const float2* wv = (const float2*)s_w;
#pragma unroll
        for (int cii = 0; cii < 4; cii++) {
            int ci = ci0 + cii;
#pragma unroll
            for (int kh = 0; kh < 3; kh++) {
                const float2* rp = (const float2*)(s_in + ci*114 + (oh + kh)*14 + ow0);
                float v[8];
#pragma unroll
                for (int m = 0; m < 4; m++) { float2 p = rp[m]; v[2*m] = p.x; v[2*m+1] = p.y; }
                float2 w[3];
#pragma unroll
                for (int kw = 0; kw < 3; kw++) w[kw] = wv[(ci*9 + kh*3 + kw)*2 + pair];
#pragma unroll
                for (int kw = 0; kw < 3; kw++)
#pragma unroll
                    for (int t = 0; t < 6; t++)
                        ffma2(acc[t], bcast2(v[kw+t]), w[kw]);
            }
        }
    }
    __syncthreads();   // all s_in reads complete before aliased writes
    {
        float* pp = s_part + threadIdx.x * 12;
#pragma unroll
        for (int t = 0; t < 6; t++) { pp[2*t] = acc[t].x; pp[2*t+1] = acc[t].y; }
    }
    __syncthreads();
    if (threadIdx.x < 288) {
        int o = threadIdx.x;
        int co_l = o / 72, pos = o % 72;
        int oh2 = pos / 12, ow = pos % 12;
        int owh2 = ow / 6, t = ow % 6;
        int pair2 = co_l >> 1, coin = co_l & 1;
        float v = b3[cb + co_l];
#pragma unroll
        for (int q = 0; q < 16; q++)
            v += s_part[(q*24 + pair2*12 + oh2*2 + owh2)*12 + t*2 + coin];
        s_c[co_l*72 + pos] = fmaxf(v, 0.f);
    }
    __syncthreads();
    if (threadIdx.x < 72) {
        int co_l = threadIdx.x / 18, cell = threadIdx.x % 18;
        int ph = cell / 6, pw = cell % 6;
        const float* c = s_c + co_l*72 + (ph*2)*12 + pw*2;
        s_p[threadIdx.x] = fmaxf(fmaxf(c[0], c[1]), fmaxf(c[12], c[13]));
    }
    __syncthreads();
    if (threadIdx.x < 4) {
        float s = 0.f;
#pragma unroll
        for (int i = 0; i < 18; i++) s += s_p[threadIdx.x*18 + i];
        g_gap[b*128 + cb + threadIdx.x] = s * (1.0f/18.0f);
    }
}

// ---------------------------------------------------------------------------
// 5. fc: coalesced. 8 lanes per output row; LDG.128; shfl-tree reduce.
__global__ void __launch_bounds__(128) fc_fused(const float* __restrict__ wl1,
                                                const float* __restrict__ bl1,
                                                const float* __restrict__ wl2,
                                                const float* __restrict__ bl2,
                                                float* __restrict__ out) {
    __shared__ float s_g[128];
    __shared__ float s_h[128];
    int b = blockIdx.x, tid = threadIdx.x;
    s_g[tid] = g_gap[b*128 + tid];
    __syncthreads();
    const float4* g4 = (const float4*)s_g;
#pragma unroll
    for (int pass = 0; pass < 8; pass++) {
        int t = pass*16 + (tid >> 3);
        int j = tid & 7;
        const float4* wr = (const float4*)(wl1 + t*128);
        float s = 0.f;
#pragma unroll
        for (int k = 0; k < 4; k++) {
            float4 w4 = wr[j + k*8];
            float4 gv = g4[j + k*8];
            s += w4.x*gv.x + w4.y*gv.y + w4.z*gv.z + w4.w*gv.w;
        }
        s += __shfl_down_sync(0xffffffffu, s, 4);
        s += __shfl_down_sync(0xffffffffu, s, 2);
        s += __shfl_down_sync(0xffffffffu, s, 1);
        if (j == 0) s_h[t] = fmaxf(s + bl1[t], 0.f);
    }
    __syncthreads();
    const float4* h4 = (const float4*)s_h;
    if (tid < 40) {
        int t = tid >> 3, j = tid & 7;
        const float4* wr = (const float4*)(wl2 + t*128);
        float s = 0.f;
#pragma unroll
        for (int k = 0; k < 4; k++) {
            float4 w4 = wr[j + k*8];
            float4 hv = h4[j + k*8];
            s += w4.x*hv.x + w4.y*hv.y + w4.z*hv.z + w4.w*hv.w;
        }
        s += __shfl_down_sync(0xffffffffu, s, 4);
        s += __shfl_down_sync(0xffffffffu, s, 2);
        s += __shfl_down_sync(0xffffffffu, s, 1);
        if (j == 0) out[b*5 + t] = s + bl2[t];
    }
}

extern "C" void kernel_launch(void* const* d_in, const int* in_sizes, int n_in,
                              void* d_out, int out_size) {
    const int*   x   = (const int*)  d_in[0];
    const float* w1  = (const float*)d_in[1];
    const float* b1  = (const float*)d_in[2];
    const float* w2  = (const float*)d_in[3];
    const float* b2  = (const float*)d_in[4];
    const float* w3  = (const float*)d_in[5];
    const float* b3  = (const float*)d_in[6];
    const float* wl1 = (const float*)d_in[7];
    const float* bl1 = (const float*)d_in[8];
    const float* wl2 = (const float*)d_in[9];
    const float* bl2 = (const float*)d_in[10];
    float* out = (float*)d_out;

    const int smem1 = (6270 + 588 + 1428) * 4;      // 33144 B
    const int smem2 = (15360 + 1600) * 4;           // 67840 B (aliased)
    const int smem3 = (7296 + 2304) * 4;            // 38400 B (aliased)
    cudaFuncSetAttribute(conv1_pool1, cudaFuncAttributeMaxDynamicSharedMemorySize, smem1);
    cudaFuncSetAttribute(conv2_pool2, cudaFuncAttributeMaxDynamicSharedMemorySize, smem2);
    cudaFuncSetAttribute(conv3_gap,   cudaFuncAttributeMaxDynamicSharedMemorySize, smem3);

    scatter_split<<<BB*CC*KSPLIT, 1024>>>(x);
    convert_grid <<<(GRIDP_N + 255) / 256, 256>>>();
    conv1_pool1  <<<BB*32, 128, smem1>>>(w1, b1);
    conv2_pool2  <<<BB*32, 480, smem2>>>(w2, b2);
    conv3_gap    <<<BB*32, 384, smem3>>>(w3, b3);
    fc_fused     <<<BB, 128>>>(wl1, bl1, wl2, bl2, out);
}